// round 16
// baseline (speedup 1.0000x reference)
#include <cuda_runtime.h>
#include <cuda_bf16.h>
#include <cstdint>

// ---------------- problem constants ----------------
#define O_N   3
#define DK    128
#define DV    512
#define BANK  8192
#define QN    4096
#define MQ    64             // queries per block
#define BN    64             // bank tile
#define NT    128            // total bank tiles (8192/64)
#define NSL   3              // bank slices (wave-quantization fix)
#define THREADS 512          // 16 warps: 2 mw x 8 nw  -> full DV=512 per block
// 1/sqrt(128) * log2(e), folded into Q so epilogue is bare ex2
#define QSCALE (0.08838834764831845f * 1.4426950408889634f)

// ---------------- smem layout (occ 1, 135 KB) ----------------
#define QS_STR 136   // 272 B rows
#define KS_STR 136
#define VS_STR 72    // 144 B rows
#define PS_STR 72
#define QS_OFF    0                        // 64*136*2 = 17408
#define KS_OFF(b) (17408 + (b) * 17408)    // x2 -> 52224 (K double buffered)
#define VS_OFF    52224                    // 512*72*2 = 73728 -> 125952 (V single)
#define PS_OFF    125952                   // 64*72*2  = 9216 -> 135168
#define LROW_OFF  135168                   // 64 f32   = 256  -> 135424
#define SMEM_BYTES 135424

// ---------------- device scratch ----------------
__device__ __nv_bfloat16 g_kT[(size_t)O_N * BANK * DK];   // [o][n][k]  6 MB
__device__ __nv_bfloat16 g_vB[(size_t)O_N * DV * BANK];   // [o][v][n] 24 MB
__device__ float g_part[(size_t)NSL * O_N * DV * QN];     // per-slice unnormalized PV (75 MB)
__device__ float g_Lp[(size_t)NSL * O_N * QN];            // per-slice exp-sums

// ---------------- helpers ----------------
static __device__ __forceinline__ uint32_t s2u(const void* p) {
    uint32_t a;
    asm("{ .reg .u64 t; cvta.to.shared.u64 t, %1; cvt.u32.u64 %0, t; }" : "=r"(a) : "l"(p));
    return a;
}
static __device__ __forceinline__ uint32_t pack2(float lo, float hi) {   // lo -> low half
    uint32_t r;
    asm("cvt.rn.bf16x2.f32 %0, %1, %2;" : "=r"(r) : "f"(hi), "f"(lo));
    return r;
}
static __device__ __forceinline__ float ex2f(float x) {
    float r; asm("ex2.approx.f32 %0, %1;" : "=f"(r) : "f"(x)); return r;
}
static __device__ __forceinline__ void ldsm4(uint32_t* r, uint32_t addr) {
    asm volatile("ldmatrix.sync.aligned.m8n8.x4.shared.b16 {%0,%1,%2,%3}, [%4];"
                 : "=r"(r[0]), "=r"(r[1]), "=r"(r[2]), "=r"(r[3]) : "r"(addr));
}
static __device__ __forceinline__ void ldsm2(uint32_t* r, uint32_t addr) {
    asm volatile("ldmatrix.sync.aligned.m8n8.x2.shared.b16 {%0,%1}, [%2];"
                 : "=r"(r[0]), "=r"(r[1]) : "r"(addr));
}
static __device__ __forceinline__ void mma16816(float* d, const uint32_t* a,
                                                uint32_t b0, uint32_t b1) {
    asm volatile(
        "mma.sync.aligned.m16n8k16.row.col.f32.bf16.bf16.f32 "
        "{%0,%1,%2,%3}, {%4,%5,%6,%7}, {%8,%9}, {%0,%1,%2,%3};"
        : "+f"(d[0]), "+f"(d[1]), "+f"(d[2]), "+f"(d[3])
        : "r"(a[0]), "r"(a[1]), "r"(a[2]), "r"(a[3]), "r"(b0), "r"(b1));
}
static __device__ __forceinline__ void cpa16(uint32_t s, const void* g) {
    asm volatile("cp.async.cg.shared.global [%0], [%1], 16;" :: "r"(s), "l"(g) : "memory");
}
static __device__ __forceinline__ void cpa_commit() {
    asm volatile("cp.async.commit_group;" ::: "memory");
}
static __device__ __forceinline__ void cpa_wait0() {
    asm volatile("cp.async.wait_group 0;" ::: "memory");
}
static __device__ __forceinline__ void cpa_wait1() {
    asm volatile("cp.async.wait_group 1;" ::: "memory");
}

// ---------------- prep: K fp32 [o][k][n] -> bf16 [o][n][k]; V fp32 -> bf16 ----------------
__global__ void prep_kernel(const float* __restrict__ keys, const float* __restrict__ values) {
    const int bid = blockIdx.x, tid = threadIdx.x;
    if (bid < O_N * (BANK / 64)) {
        __shared__ float tile[128][65];
        const int o = bid / (BANK / 64), nt = bid % (BANK / 64), n0 = nt * 64;
        const float* kg = keys + (size_t)o * DK * BANK;
#pragma unroll
        for (int i = 0; i < 8; ++i) {
            int idx = tid + 256 * i;
            int k = idx >> 4, f4 = idx & 15;
            const float4 x = *(const float4*)(kg + (size_t)k * BANK + n0 + f4 * 4);
            tile[k][f4 * 4 + 0] = x.x; tile[k][f4 * 4 + 1] = x.y;
            tile[k][f4 * 4 + 2] = x.z; tile[k][f4 * 4 + 3] = x.w;
        }
        __syncthreads();
        uint32_t* outp = (uint32_t*)g_kT;
#pragma unroll
        for (int i = 0; i < 16; ++i) {
            int u = tid + 256 * i;
            int n = u >> 6, k2 = u & 63;
            outp[(size_t)o * BANK * 64 + (size_t)(n0 + n) * 64 + k2] =
                pack2(tile[2 * k2][n], tile[2 * k2 + 1][n]);
        }
    } else {
        const int vb = bid - O_N * (BANK / 64);
        const float4* src = (const float4*)values;
        uint2* dst = (uint2*)g_vB;
#pragma unroll
        for (int i = 0; i < 16; ++i) {
            size_t idx = (size_t)vb * 4096 + tid + 256 * i;
            const float4 x = src[idx];
            uint2 p;
            p.x = pack2(x.x, x.y);
            p.y = pack2(x.z, x.w);
            dst[idx] = p;
        }
    }
}
#define PREP_BLOCKS (O_N * (BANK / 64) + (O_N * DV * BANK) / 16384)   // 384 + 768

// ---------------- async loaders (512 threads) ----------------
static __device__ __forceinline__ void load_K_async(uint32_t sb, int o, int buf, int t, int tid) {
    const int n0 = t * BN;
    const uint32_t ks = sb + KS_OFF(buf);
    const __nv_bfloat16* kT = g_kT + (size_t)o * BANK * DK + (size_t)n0 * DK;
#pragma unroll
    for (int i = 0; i < 2; ++i) {            // 64 rows x 16 chunks = 1024
        int c = tid + THREADS * i;
        int n = c >> 4, k16 = c & 15;
        cpa16(ks + (uint32_t)(n * (KS_STR * 2) + k16 * 16), kT + (size_t)n * DK + k16 * 8);
    }
    cpa_commit();
}
static __device__ __forceinline__ void load_V_async(uint32_t sb, int o, int t, int tid) {
    const int n0 = t * BN;
    const uint32_t vs = sb + VS_OFF;
    const __nv_bfloat16* vB = g_vB + (size_t)o * DV * BANK;
#pragma unroll
    for (int i = 0; i < 8; ++i) {            // 512 rows x 8 chunks = 4096
        int c = tid + THREADS * i;
        int v = c >> 3, n16 = c & 7;
        cpa16(vs + (uint32_t)(v * (VS_STR * 2) + n16 * 16), vB + (size_t)v * BANK + n0 + n16 * 8);
    }
    cpa_commit();
}

// ---------------- main fused kernel (512 thr, full DV, bank-sliced) ----------------
__global__ __launch_bounds__(THREADS, 1)
void attn_mma_kernel(const float* __restrict__ q_in) {
    extern __shared__ unsigned char smem[];
    const uint32_t sb = s2u(smem);
    const int tid = threadIdx.x;
    const int l = tid & 31;
    const int wid = tid >> 5;          // 0..15
    const int mw = wid >> 3;           // 0..1 : 32-query group
    const int nw = wid & 7;            // 0..7 : QK n8 group / PV 64-v group
    const int bx = blockIdx.x;
    const int slice = bx >> 6;                 // 0..2
    const int q0 = (bx & 63) * MQ;
    const int o = blockIdx.y;
    const int t0 = slice * 43;
    const int t1 = (slice == 2) ? NT : t0 + 43;   // 43 / 43 / 42 tiles

    if (tid < MQ) *(float*)(smem + LROW_OFF + tid * 4) = 0.0f;

    // Q -> Qs[q][k] bf16, scaled (one-time)
    {
        __nv_bfloat16* qs = (__nv_bfloat16*)(smem + QS_OFF);
#pragma unroll
        for (int i = 0; i < 4; ++i) {          // 2048 float4
            int idx = tid + THREADS * i;
            int k = idx >> 4, q4 = (idx & 15) * 4;
            const float4 x = *(const float4*)(q_in + (size_t)k * QN + q0 + q4);
            qs[(q4 + 0) * QS_STR + k] = __float2bfloat16(x.x * QSCALE);
            qs[(q4 + 1) * QS_STR + k] = __float2bfloat16(x.y * QSCALE);
            qs[(q4 + 2) * QS_STR + k] = __float2bfloat16(x.z * QSCALE);
            qs[(q4 + 3) * QS_STR + k] = __float2bfloat16(x.w * QSCALE);
        }
    }
    load_K_async(sb, o, t0 & 1, t0, tid);
    load_V_async(sb, o, t0, tid);
    cpa_wait0();
    __syncthreads();

    float acc[2][8][4];
#pragma unroll
    for (int a = 0; a < 2; ++a)
#pragma unroll
        for (int b = 0; b < 8; ++b)
#pragma unroll
            for (int c = 0; c < 4; ++c) acc[a][b][c] = 0.0f;
    float lsum[4] = {0.f, 0.f, 0.f, 0.f};

    const int aRow = l & 15;
    const int aKhi = l >> 4;
    const int bRow = (l & 7) + ((l >> 4) << 3);
    const int bKhi = (l >> 3) & 1;

    const uint32_t qsb = sb + QS_OFF + (uint32_t)(((mw * 32 + aRow) * QS_STR + 8 * aKhi) * 2);
    const uint32_t psb = sb + PS_OFF + (uint32_t)(((mw * 32 + aRow) * PS_STR + 8 * aKhi) * 2);
    // QK B-frag (ldsm.x2): lanes 0-15 rows = nw*8 + (l&7), k-half by (l>>3)&1
    const uint32_t kfo = (uint32_t)(((nw * 8 + (l & 7)) * KS_STR + 8 * ((l >> 3) & 1)) * 2);
    const int g8 = l >> 2, t2 = (l & 3) * 2;

    for (int g = t0; g < t1; ++g) {
        const int buf = g & 1;
        const bool more = (g + 1 < t1);
        if (more) load_K_async(sb, o, (g + 1) & 1, g + 1, tid);
        // ---- QK: S[64q x 64n], warp covers [mw 32q, nw 8n] ----
        float sc[2][4];
#pragma unroll
        for (int a = 0; a < 2; ++a)
#pragma unroll
            for (int c = 0; c < 4; ++c) sc[a][c] = 0.0f;
        {
            const uint32_t ksb = sb + KS_OFF(buf) + kfo;
#pragma unroll
            for (int s = 0; s < 8; ++s) {
                uint32_t a0[4], a1[4], b[2];
                ldsm4(a0, qsb + s * 32);
                ldsm4(a1, qsb + 16 * QS_STR * 2 + s * 32);
                ldsm2(b, ksb + s * 32);
                mma16816(sc[0], a0, b[0], b[1]);
                mma16816(sc[1], a1, b[0], b[1]);
            }
        }
        // ---- exp -> Ps, lsum ----
#pragma unroll
        for (int mf = 0; mf < 2; ++mf) {
            const int col = nw * 8 + t2;
            const int row = mw * 32 + mf * 16 + g8;
            float p0 = ex2f(sc[mf][0]), p1 = ex2f(sc[mf][1]);
            *(uint32_t*)(smem + PS_OFF + ((size_t)row * PS_STR + col) * 2) = pack2(p0, p1);
            float p2 = ex2f(sc[mf][2]), p3 = ex2f(sc[mf][3]);
            *(uint32_t*)(smem + PS_OFF + ((size_t)(row + 8) * PS_STR + col) * 2) = pack2(p2, p3);
            lsum[mf * 2 + 0] += p0 + p1;
            lsum[mf * 2 + 1] += p2 + p3;
        }
        if (more) cpa_wait1(); else cpa_wait0();
        __syncthreads();   // Ps + Vs visible
        // ---- PV: acc[mw 32q, nw 64v] += P[32q,64n] * V[64n,64v] ----
        {
            const uint32_t vsb = sb + VS_OFF +
                (uint32_t)(((nw * 64 + bRow) * VS_STR + 8 * bKhi) * 2);
#pragma unroll
            for (int s = 0; s < 4; ++s) {
                uint32_t a0[4], a1[4];
                ldsm4(a0, psb + s * 32);
                ldsm4(a1, psb + 16 * PS_STR * 2 + s * 32);
#pragma unroll
                for (int j = 0; j < 4; ++j) {
                    uint32_t b[4];
                    ldsm4(b, vsb + (uint32_t)(j * 16 * VS_STR * 2) + s * 32);
                    mma16816(acc[0][2 * j],     a0, b[0], b[1]);
                    mma16816(acc[0][2 * j + 1], a0, b[2], b[3]);
                    mma16816(acc[1][2 * j],     a1, b[0], b[1]);
                    mma16816(acc[1][2 * j + 1], a1, b[2], b[3]);
                }
            }
        }
        __syncthreads();   // Vs free
        if (more) {
            load_V_async(sb, o, g + 1, tid);
            cpa_wait1();   // K(g+1) done (older group)
            __syncthreads();
        }
    }

    // ---- reduce l across lanes (t bits) then warps (shared atomics) ----
#pragma unroll
    for (int j = 0; j < 4; ++j) {
        lsum[j] += __shfl_xor_sync(0xffffffffu, lsum[j], 1);
        lsum[j] += __shfl_xor_sync(0xffffffffu, lsum[j], 2);
    }
    if ((l & 3) == 0) {
        float* lrow = (float*)(smem + LROW_OFF);
#pragma unroll
        for (int j = 0; j < 4; ++j)
            atomicAdd(&lrow[mw * 32 + (j >> 1) * 16 + g8 + 8 * (j & 1)], lsum[j]);
    }
    __syncthreads();
    if (tid < MQ)
        g_Lp[((size_t)slice * O_N + o) * QN + q0 + tid] = *(float*)(smem + LROW_OFF + tid * 4);

    // ---- store unnormalized partials to g_part (full 512 v per block) ----
    float* ob = g_part + ((size_t)(slice * O_N + o) * DV) * QN + q0;
#pragma unroll
    for (int mf = 0; mf < 2; ++mf)
#pragma unroll
        for (int nf = 0; nf < 8; ++nf) {
            const int col = nw * 64 + nf * 8 + t2;
            const int r0 = mw * 32 + mf * 16 + g8;
            ob[(size_t)col * QN + r0]           = acc[mf][nf][0];
            ob[(size_t)(col + 1) * QN + r0]     = acc[mf][nf][1];
            ob[(size_t)col * QN + r0 + 8]       = acc[mf][nf][2];
            ob[(size_t)(col + 1) * QN + r0 + 8] = acc[mf][nf][3];
        }
}

// ---------------- normalize: out = (sum of 3 slices) / (sum of 3 L) ----------------
__global__ void norm_kernel(float* __restrict__ out) {
    const size_t i = (size_t)blockIdx.x * blockDim.x + threadIdx.x;  // float4 index
    const size_t SL = (size_t)O_N * DV * QN / 4;
    const size_t LS = (size_t)O_N * QN / 4;
    const int q4 = (int)(i & (QN / 4 - 1));
    const size_t rest = i >> 10;
    const int v = (int)(rest & (DV - 1));
    const int o = (int)(rest >> 9);
    const float4* P = (const float4*)g_part;
    const float4 a = P[i], b = P[i + SL], c = P[i + 2 * SL];
    const float4* L = (const float4*)g_Lp;
    const size_t li = (size_t)o * (QN / 4) + q4;
    const float4 l0 = L[li], l1 = L[li + LS], l2 = L[li + 2 * LS];
    float4 r;
    r.x = (a.x + b.x + c.x) / (l0.x + l1.x + l2.x);
    r.y = (a.y + b.y + c.y) / (l0.y + l1.y + l2.y);
    r.z = (a.z + b.z + c.z) / (l0.z + l1.z + l2.z);
    r.w = (a.w + b.w + c.w) / (l0.w + l1.w + l2.w);
    ((float4*)out)[(size_t)o * (1024 * QN / 4) + (size_t)v * (QN / 4) + q4] = r;
}

// ---------------- q_out broadcast (channels [512,1024) per object) ----------------
__global__ void copy_qout_kernel(const float* __restrict__ qo, float* __restrict__ out) {
    size_t i = (size_t)blockIdx.x * blockDim.x + threadIdx.x;
    const float4 v = reinterpret_cast<const float4*>(qo)[i];
#pragma unroll
    for (int o = 0; o < O_N; ++o)
        reinterpret_cast<float4*>(out + (size_t)o * 1024 * QN + (size_t)DV * QN)[i] = v;
}

extern "C" void kernel_launch(void* const* d_in, const int* in_sizes, int n_in,
                              void* d_out, int out_size) {
    const float* keys   = (const float*)d_in[0];  // [3,128,8192]
    const float* values = (const float*)d_in[1];  // [3,512,8192]
    const float* q_in   = (const float*)d_in[2];  // [1,128,4096]
    const float* q_out  = (const float*)d_in[3];  // [1,512,4096]
    float* out = (float*)d_out;                   // [1,3,1024,4096]

    (void)cudaFuncSetAttribute(attn_mma_kernel,
                               cudaFuncAttributeMaxDynamicSharedMemorySize, SMEM_BYTES);

    // 4 launches/call: prep(0), attn(1), norm(2), copy(3) -> ncu "-s 5" = attn.
    prep_kernel<<<PREP_BLOCKS, 256>>>(keys, values);

    dim3 grid(64 * NSL, O_N);   // 192 x 3 = 576 blocks, 512 threads each
    attn_mma_kernel<<<grid, THREADS, SMEM_BYTES>>>(q_in);

    norm_kernel<<<(O_N * DV * QN / 4) / 256, 256>>>(out);
    copy_qout_kernel<<<(DV * QN / 4) / 256, 256>>>(q_out, out);
}